// round 14
// baseline (speedup 1.0000x reference)
#include <cuda_runtime.h>
#include <cuda_fp16.h>
#include <math.h>
#include <stdint.h>

// Swin-V2 shifted-window MHA: split-fp16 tensor-core (mma.m16n8k16.f16).
// One CTA (512 thr = 16 warps) per window; 2048 CTAs; 4 warps/SMSP.
// Projections: 2-term split (Ah*Bh + Al*Bh), W hi-only. Attention: 3-term,
// with the relative-position bias pre-loaded INTO the S accumulators (the
// MMA C-operand performs the add; saves 32 live registers + an add pass).
// Weights read directly from global (L2-resident, fragment-ordered LDG.64,
// 2-chunk-ahead prefetch in projections).
//
// "F4" layout (x, Q, K, O): u32 rows of XSTR; chunk g (16 values), group tg:
//   uint4 at row*XSTR + g*16 + tg*4 = {hi(pair g8+tg), hi(pair g8+tg+4), lo, lo}

#define XSTR 272
#define VSTR 64

#define OFF_X   0        // x F4 (17408); VT F4 (16384) overlays after V gemm
#define OFF_Q   17408    // Q F4 -> O F4
#define OFF_K   34816    // K F4
#define SMEM_U32 52224   // 208896 bytes

__device__ uint32_t g_wh[4 * 16 * 256 * 8];   // [w][kc][n][8] fp16-hi pairs
__device__ float    g_bias[4 * 8 * 64 * 64];  // [wtype][h][n][m], masked=-1e30

__device__ __forceinline__ uint32_t pack2h(float x, float y) {
    uint32_t r;
    asm("cvt.rn.f16x2.f32 %0, %1, %2;" : "=r"(r) : "f"(y), "f"(x));  // y->hi, x->lo
    return r;
}
__device__ __forceinline__ void split2h(float x, float y, uint32_t& h, uint32_t& l) {
    uint32_t hh;
    asm("cvt.rn.f16x2.f32 %0, %1, %2;" : "=r"(hh) : "f"(y), "f"(x));
    __half2 h2 = *reinterpret_cast<__half2*>(&hh);
    float rx = x - __half2float(__low2half(h2));
    float ry = y - __half2float(__high2half(h2));
    uint32_t ll;
    asm("cvt.rn.f16x2.f32 %0, %1, %2;" : "=r"(ll) : "f"(ry), "f"(rx));
    h = hh; l = ll;
}

#define MMAH(C, A0, A1, A2, A3, B0, B1)                                       \
    asm volatile("mma.sync.aligned.m16n8k16.row.col.f32.f16.f16.f32 "         \
                 "{%0,%1,%2,%3}, {%4,%5,%6,%7}, {%8,%9}, {%0,%1,%2,%3};"      \
                 : "+f"(C[0]), "+f"(C[1]), "+f"(C[2]), "+f"(C[3])             \
                 : "r"(A0), "r"(A1), "r"(A2), "r"(A3), "r"(B0), "r"(B1))

// ---------------------------------------------------------------------------
// Prep: blocks 0..63 = weight split; blocks 64..288 = masked bias table.
// ---------------------------------------------------------------------------
__global__ void prep_kernel(const float* __restrict__ w1,
                            const float* __restrict__ b1,
                            const float* __restrict__ w2,
                            const float* __restrict__ wq,
                            const float* __restrict__ wk,
                            const float* __restrict__ wv,
                            const float* __restrict__ wo)
{
    __shared__ float ws[8][8];
    __shared__ float bv[8];
    int t = threadIdx.x;

    if (blockIdx.x < 64) {
        const float* wsrc[4] = {wq, wk, wv, wo};
        int w = blockIdx.x >> 4, kc = blockIdx.x & 15;
        const float* src = wsrc[w] + t * 256 + kc * 16;
        float v[16];
#pragma unroll
        for (int i = 0; i < 4; i++) {
            float4 q = *reinterpret_cast<const float4*>(src + i * 4);
            v[4*i] = q.x; v[4*i+1] = q.y; v[4*i+2] = q.z; v[4*i+3] = q.w;
        }
        uint32_t u[8];
#pragma unroll
        for (int tg = 0; tg < 4; tg++) {
            u[tg*2]   = pack2h(v[2*tg],   v[2*tg+1]);
            u[tg*2+1] = pack2h(v[8+2*tg], v[9+2*tg]);
        }
        uint32_t* dst = g_wh + (blockIdx.x * 256 + t) * 8;
        *reinterpret_cast<uint4*>(dst)     = make_uint4(u[0], u[1], u[2], u[3]);
        *reinterpret_cast<uint4*>(dst + 4) = make_uint4(u[4], u[5], u[6], u[7]);
        return;
    }

    int cell = blockIdx.x - 64;           // 0..224
    int a = cell / 15, bcol = cell % 15;
    float ra = (a - 7) * (8.0f / 7.0f);
    float rb = (bcol - 7) * (8.0f / 7.0f);
    float va = (ra >= 0.f ? 1.f : -1.f) * log2f(fabsf(ra) + 1.f) * (1.f / 3.f);
    float vb = (rb >= 0.f ? 1.f : -1.f) * log2f(fabsf(rb) + 1.f) * (1.f / 3.f);

    int j1 = t, j2 = t + 256;
    float h1 = fmaxf(va * w1[j1 * 2] + vb * w1[j1 * 2 + 1] + b1[j1], 0.f);
    float h2 = fmaxf(va * w1[j2 * 2] + vb * w1[j2 * 2 + 1] + b1[j2], 0.f);

    float p[8];
#pragma unroll
    for (int h = 0; h < 8; h++)
        p[h] = h1 * w2[h * 512 + j1] + h2 * w2[h * 512 + j2];
#pragma unroll
    for (int h = 0; h < 8; h++)
#pragma unroll
        for (int off = 16; off; off >>= 1)
            p[h] += __shfl_xor_sync(0xffffffffu, p[h], off);

    int warp = t >> 5, lane = t & 31;
    if (lane == 0) {
#pragma unroll
        for (int h = 0; h < 8; h++) ws[warp][h] = p[h];
    }
    __syncthreads();
    if (t < 8) {
        float s = 0.f;
#pragma unroll
        for (int w = 0; w < 8; w++) s += ws[w][t];
        bv[t] = 16.f / (1.f + expf(-s));
    }
    __syncthreads();

    int da = a - 7, db = bcol - 7;
    int cntA = 8 - abs(da), cntB = 8 - abs(db);
    int rn0 = da > 0 ? da : 0, cn0 = db > 0 ? db : 0;
    int total = cntA * cntB * 32;
    for (int idx = t; idx < total; idx += 256) {
        int tmp = idx;
        int h = tmp & 7; tmp >>= 3;
        int wt_ = tmp & 3; tmp >>= 2;
        int pa = tmp / cntB, pb = tmp - pa * cntB;
        int rn = rn0 + pa, cn = cn0 + pb;
        int rm = rn - da, cm = cn - db;
        int wh = wt_ >> 1, ww = wt_ & 1;
        int ghn = wh * 8 + rn, gwn = ww * 8 + cn;
        int ghm = wh * 8 + rm, gwm = ww * 8 + cm;
        int gn = ((ghn < 8) ? 0 : (ghn < 12 ? 1 : 2)) * 3 + ((gwn < 8) ? 0 : (gwn < 12 ? 1 : 2));
        int gm = ((ghm < 8) ? 0 : (ghm < 12 ? 1 : 2)) * 3 + ((gwm < 8) ? 0 : (gwm < 12 ? 1 : 2));
        float val = (gn == gm) ? bv[h] : -1e30f;
        g_bias[((wt_ * 8 + h) * 64 + rn * 8 + cn) * 64 + rm * 8 + cm] = val;
    }
}

// ---- one 16-wide k-chunk, 16x64 warp tile (16 MMAs, hi then lo sweep) ----
#define PROJ_CHUNK(B, kc)                                                     \
    do {                                                                      \
        const uint32_t* a_ = ap + (kc) * 16;                                  \
        const uint4 A0 = *reinterpret_cast<const uint4*>(a_);                 \
        const uint4 A1 = *reinterpret_cast<const uint4*>(a_ + 8 * XSTR);      \
        _Pragma("unroll")                                                     \
        for (int nf = 0; nf < 8; nf++)                                        \
            MMAH(acc[nf], A0.x, A1.x, A0.y, A1.y, B[nf].x, B[nf].y);          \
        _Pragma("unroll")                                                     \
        for (int nf = 0; nf < 8; nf++)                                        \
            MMAH(acc[nf], A0.z, A1.z, A0.w, A1.w, B[nf].x, B[nf].y);          \
    } while (0)

#define PROJ_LD(B, c)                                                         \
    do {                                                                      \
        _Pragma("unroll")                                                     \
        for (int nf = 0; nf < 8; nf++) B[nf] = __ldg(gb + (c) * 1024 + nf * 32); \
    } while (0)

// ---------------------------------------------------------------------------
// Projection GEMM (2-term): out(64x256) = A(F4 smem) @ Whi^T. Warp 16x64.
// 2-chunk-ahead prefetch via 4-buffer static rotation.
// ---------------------------------------------------------------------------
__device__ __forceinline__ void gemm_proj(
    const uint32_t* __restrict__ src, const uint32_t* __restrict__ gw,
    float acc[8][4], int rbase, int warpN, int gid, int tg)
{
#pragma unroll
    for (int nf = 0; nf < 8; nf++)
#pragma unroll
        for (int j = 0; j < 4; j++) acc[nf][j] = 0.f;

    const uint2* gb = reinterpret_cast<const uint2*>(gw) + (warpN * 64 + gid) * 4 + tg;
    const uint32_t* ap = src + (rbase + gid) * XSTR + tg * 4;

    uint2 Ba[8], Bb[8], Bc[8], Bd[8];
    PROJ_LD(Ba, 0);
    PROJ_LD(Bb, 1);

#pragma unroll 1
    for (int it = 0; it < 4; it++) {
        const int c = 4 * it;
        PROJ_LD(Bc, c + 2);
        PROJ_CHUNK(Ba, c);
        PROJ_LD(Bd, c + 3);
        PROJ_CHUNK(Bb, c + 1);
        const int c4 = (c + 4 < 16) ? c + 4 : 15;
        PROJ_LD(Ba, c4);
        PROJ_CHUNK(Bc, c + 2);
        const int c5 = (c + 5 < 16) ? c + 5 : 15;
        PROJ_LD(Bb, c5);
        PROJ_CHUNK(Bd, c + 3);
    }
}

// ---- VT chunk: 16 d-rows x 64 tokens, 16 MMAs (hi sweep then lo sweep) ----
#define VT_CHUNK(W, kc)                                                       \
    do {                                                                      \
        const uint32_t* xp = xp0 + (kc) * 16;                                 \
        uint4 Xv[8];                                                          \
        _Pragma("unroll")                                                     \
        for (int nf = 0; nf < 8; nf++)                                        \
            Xv[nf] = *reinterpret_cast<const uint4*>(xp + nf * 8 * XSTR);     \
        _Pragma("unroll")                                                     \
        for (int nf = 0; nf < 8; nf++)                                        \
            MMAH(av[nf], W[0].x, W[1].x, W[0].y, W[1].y, Xv[nf].x, Xv[nf].y); \
        _Pragma("unroll")                                                     \
        for (int nf = 0; nf < 8; nf++)                                        \
            MMAH(av[nf], W[0].x, W[1].x, W[0].y, W[1].y, Xv[nf].z, Xv[nf].w); \
    } while (0)

#define VT_LD(W, c)                                                           \
    do {                                                                      \
        W[0] = __ldg(ga + (c) * 1024);                                        \
        W[1] = __ldg(ga + (c) * 1024 + 32);                                   \
    } while (0)

// ---------------------------------------------------------------------------
// VT GEMM (2-term): VT(256x64) = Wv_hi @ x^T. Warp: 16 d-rows. Ends barrier.
// ---------------------------------------------------------------------------
__device__ __forceinline__ void gemm_vt(
    const uint32_t* __restrict__ x, const uint32_t* __restrict__ gw,
    float av[8][4], int warp, int gid, int tg)
{
#pragma unroll
    for (int nf = 0; nf < 8; nf++)
#pragma unroll
        for (int j = 0; j < 4; j++) av[nf][j] = 0.f;

    const uint2* ga = reinterpret_cast<const uint2*>(gw) + (warp * 16 + gid) * 4 + tg;
    const uint32_t* xp0 = x + gid * XSTR + tg * 4;

    uint2 Wa[2], Wb[2], Wc[2], Wd[2];
    VT_LD(Wa, 0);
    VT_LD(Wb, 1);

#pragma unroll 1
    for (int it = 0; it < 4; it++) {
        const int c = 4 * it;
        VT_LD(Wc, c + 2);
        VT_CHUNK(Wa, c);
        VT_LD(Wd, c + 3);
        VT_CHUNK(Wb, c + 1);
        const int c4 = (c + 4 < 16) ? c + 4 : 15;
        VT_LD(Wa, c4);
        VT_CHUNK(Wc, c + 2);
        const int c5 = (c + 5 < 16) ? c + 5 : 15;
        VT_LD(Wb, c5);
        VT_CHUNK(Wd, c + 3);
    }
    __syncthreads();   // all X reads complete before VTS overwrite
}

// ---------------------------------------------------------------------------
__global__ __launch_bounds__(512, 1)
void swin_kernel(const float* __restrict__ img,
                 const float* __restrict__ bq, const float* __restrict__ bk,
                 const float* __restrict__ bv, const float* __restrict__ bo,
                 const float* __restrict__ ls,
                 float* __restrict__ out)
{
    extern __shared__ uint32_t smu[];
    uint32_t* X   = smu + OFF_X;
    uint32_t* QS  = smu + OFF_Q;
    uint32_t* KS  = smu + OFF_K;
    uint32_t* VTS = smu + OFF_X;        // overlays X after V gemm

    const int t    = threadIdx.x;
    const int lane = t & 31;
    const int warp = t >> 5;            // 0..15
    const int warpM = warp & 3, warpN = warp >> 2;
    const int gid = lane >> 2, tg = lane & 3;
    const int blk = blockIdx.x;
    const int b   = blk >> 2;
    const int wh  = (blk >> 1) & 1, ww = blk & 1;
    const int wtype = blk & 3;

    // ---- load shifted window -> x F4 split (fp16 hi/lo)
    const float* imgb = img + (size_t)b * (16 * 16 * 256);
#pragma unroll
    for (int i = 0; i < 8; i++) {
        int f = i * 512 + t;            // float4 index
        int tok = f >> 6, c4 = f & 63;
        int r = tok >> 3, c = tok & 7;
        int ih = (wh * 8 + r + 12) & 15;
        int iw = (ww * 8 + c + 12) & 15;
        float4 v = *reinterpret_cast<const float4*>(&imgb[(ih * 16 + iw) * 256 + c4 * 4]);
        uint32_t h0, l0, h1, l1;
        split2h(v.x, v.y, h0, l0);
        split2h(v.z, v.w, h1, l1);
        int p0 = 2 * c4;
        int g = p0 >> 3, pos = p0 & 7;
        int tgs = pos & 3, slot = pos >> 2;
        uint32_t* base = X + tok * XSTR + g * 16 + slot;
        base[tgs * 4]           = h0;
        base[(tgs + 1) * 4]     = h1;
        base[tgs * 4 + 2]       = l0;
        base[(tgs + 1) * 4 + 2] = l1;
    }
    __syncthreads();   // X visible to all warps

    float acc[8][4];
    const int rbase = warpM * 16;
    const int r0w = rbase + gid, r1w = r0w + 8;

    // ---- Q = x wq^T + bq, cosine-normalize * scale, split -> QS
    gemm_proj(X, g_wh + 0 * 32768, acc, rbase, warpN, gid, tg);
    {
#pragma unroll
        for (int nf = 0; nf < 8; nf++) {
            float2 bb = *reinterpret_cast<const float2*>(bq + warpN * 64 + nf * 8 + 2 * tg);
            acc[nf][0] += bb.x; acc[nf][1] += bb.y;
            acc[nf][2] += bb.x; acc[nf][3] += bb.y;
        }
#pragma unroll
        for (int g = 0; g < 2; g++) {
            float ss0 = 0.f, ss1 = 0.f;
#pragma unroll
            for (int i = 0; i < 4; i++) {
                float* C = acc[4*g+i];
                ss0 += C[0]*C[0] + C[1]*C[1];
                ss1 += C[2]*C[2] + C[3]*C[3];
            }
            ss0 += __shfl_xor_sync(0xffffffffu, ss0, 1);
            ss0 += __shfl_xor_sync(0xffffffffu, ss0, 2);
            ss1 += __shfl_xor_sync(0xffffffffu, ss1, 1);
            ss1 += __shfl_xor_sync(0xffffffffu, ss1, 2);
            float sc = __expf(fminf(ls[warpN * 2 + g], 4.6051702f));
            float k0 = sc * rsqrtf(fmaxf(ss0, 1e-24f));
            float k1 = sc * rsqrtf(fmaxf(ss1, 1e-24f));
#pragma unroll
            for (int u = 0; u < 2; u++) {
                int ne = 4*g + 2*u, no = ne + 1;
                int ch = warpN * 4 + 2*g + u;
                uint32_t He, Le, Ho, Lo;
                split2h(acc[ne][0]*k0, acc[ne][1]*k0, He, Le);
                split2h(acc[no][0]*k0, acc[no][1]*k0, Ho, Lo);
                *reinterpret_cast<uint4*>(QS + r0w*XSTR + ch*16 + tg*4) = make_uint4(He, Ho, Le, Lo);
                split2h(acc[ne][2]*k1, acc[ne][3]*k1, He, Le);
                split2h(acc[no][2]*k1, acc[no][3]*k1, Ho, Lo);
                *reinterpret_cast<uint4*>(QS + r1w*XSTR + ch*16 + tg*4) = make_uint4(He, Ho, Le, Lo);
            }
        }
    }

    // ---- K = x wk^T + bk, normalize, split -> KS
    gemm_proj(X, g_wh + 1 * 32768, acc, rbase, warpN, gid, tg);
    {
#pragma unroll
        for (int nf = 0; nf < 8; nf++) {
            float2 bb = *reinterpret_cast<const float2*>(bk + warpN * 64 + nf * 8 + 2 * tg);
            acc[nf][0] += bb.x; acc[nf][1] += bb.y;
            acc[nf][2] += bb.x; acc[nf][3] += bb.y;
        }
#pragma unroll
        for (int g = 0; g < 2; g++) {
            float ss0 = 0.f, ss1 = 0.f;
#pragma unroll
            for (int i = 0; i < 4; i++) {
                float* C = acc[4*g+i];
                ss0 += C[0]*C[0] + C[1]*C[1];
                ss1 += C[2]*C[2] + C[3]*C[3];
            }
            ss0 += __shfl_xor_sync(0xffffffffu, ss0, 1);
            ss0 += __shfl_xor_sync(0xffffffffu, ss0, 2);
            ss1 += __shfl_xor_sync(0xffffffffu, ss1, 1);
            ss1 += __shfl_xor_sync(0xffffffffu, ss1, 2);
            float k0 = rsqrtf(fmaxf(ss0, 1e-24f));
            float k1 = rsqrtf(fmaxf(ss1, 1e-24f));
#pragma unroll
            for (int u = 0; u < 2; u++) {
                int ne = 4*g + 2*u, no = ne + 1;
                int ch = warpN * 4 + 2*g + u;
                uint32_t He, Le, Ho, Lo;
                split2h(acc[ne][0]*k0, acc[ne][1]*k0, He, Le);
                split2h(acc[no][0]*k0, acc[no][1]*k0, Ho, Lo);
                *reinterpret_cast<uint4*>(KS + r0w*XSTR + ch*16 + tg*4) = make_uint4(He, Ho, Le, Lo);
                split2h(acc[ne][2]*k1, acc[ne][3]*k1, He, Le);
                split2h(acc[no][2]*k1, acc[no][3]*k1, Ho, Lo);
                *reinterpret_cast<uint4*>(KS + r1w*XSTR + ch*16 + tg*4) = make_uint4(He, Ho, Le, Lo);
            }
        }
    }

    // ---- VT = wv x^T + bv (transposed V), F4 split -> VTS (overlays X)
    {
        float av[8][4];
        gemm_vt(X, g_wh + 2 * 32768, av, warp, gid, tg);
        int d0 = warp * 16 + gid, d1 = d0 + 8;
        float bv0 = bv[d0], bv1 = bv[d1];
#pragma unroll
        for (int kp = 0; kp < 4; kp++) {
            int ne = 2 * kp, no = ne + 1;
            uint32_t e0, f0, e1, f1;
            split2h(av[ne][0] + bv0, av[ne][1] + bv0, e0, f0);
            split2h(av[no][0] + bv0, av[no][1] + bv0, e1, f1);
            *reinterpret_cast<uint4*>(VTS + d0 * VSTR + ((kp + d0) & 3) * 16 + tg * 4) =
                make_uint4(e0, e1, f0, f1);
            split2h(av[ne][2] + bv1, av[ne][3] + bv1, e0, f0);
            split2h(av[no][2] + bv1, av[no][3] + bv1, e1, f1);
            *reinterpret_cast<uint4*>(VTS + d1 * VSTR + ((kp + d1) & 3) * 16 + tg * 4) =
                make_uint4(e0, e1, f0, f1);
        }
    }
    __syncthreads();   // QS/KS/VTS all visible before attention

    // ---- attention: warp = (half, head). Each warp: 2 mt tiles of 16 rows.
    //      S accumulators INITIALIZED with masked bias (MMA C-op adds);
    //      softmax norm deferred past PV MMAs.
    {
        const int h = warp & 7;
        const int half = warp >> 3;
        const float NEG_INF = __int_as_float(0xff800000);
        const float* bias = g_bias + (wtype * 8 + h) * 4096;

#pragma unroll 1
        for (int i = 0; i < 2; i++) {
            const int mt = half * 2 + i;
            int r0 = mt * 16 + gid, r1 = r0 + 8;

            float S[8][4];
#pragma unroll
            for (int nt = 0; nt < 8; nt++) {
                float2 b0 = *reinterpret_cast<const float2*>(bias + r0 * 64 + nt * 8 + 2 * tg);
                float2 b1 = *reinterpret_cast<const float2*>(bias + r1 * 64 + nt * 8 + 2 * tg);
                S[nt][0] = b0.x; S[nt][1] = b0.y;
                S[nt][2] = b1.x; S[nt][3] = b1.y;
            }
#pragma unroll
            for (int kc = 0; kc < 2; kc++) {
                const uint4 A0 = *reinterpret_cast<const uint4*>(
                    QS + r0 * XSTR + (2 * h + kc) * 16 + tg * 4);
                const uint4 A1 = *reinterpret_cast<const uint4*>(
                    QS + r1 * XSTR + (2 * h + kc) * 16 + tg * 4);
#pragma unroll
                for (int gq = 0; gq < 2; gq++) {
                    uint4 Bv[4];
#pragma unroll
                    for (int j = 0; j < 4; j++)
                        Bv[j] = *reinterpret_cast<const uint4*>(
                            KS + ((gq * 4 + j) * 8 + gid) * XSTR + (2 * h + kc) * 16 + tg * 4);
#pragma unroll
                    for (int j = 0; j < 4; j++)
                        MMAH(S[gq*4+j], A0.x, A1.x, A0.y, A1.y, Bv[j].x, Bv[j].y);
#pragma unroll
                    for (int j = 0; j < 4; j++)
                        MMAH(S[gq*4+j], A0.z, A1.z, A0.w, A1.w, Bv[j].x, Bv[j].y);
#pragma unroll
                    for (int j = 0; j < 4; j++)
                        MMAH(S[gq*4+j], A0.x, A1.x, A0.y, A1.y, Bv[j].z, Bv[j].w);
                }
            }
            float mx0 = NEG_INF, mx1 = NEG_INF;
#pragma unroll
            for (int nt = 0; nt < 8; nt++) {
                mx0 = fmaxf(mx0, fmaxf(S[nt][0], S[nt][1]));
                mx1 = fmaxf(mx1, fmaxf(S[nt][2], S[nt][3]));
            }
            mx0 = fmaxf(mx0, __shfl_xor_sync(0xffffffffu, mx0, 1));
            mx0 = fmaxf(mx0, __shfl_xor_sync(0xffffffffu, mx0, 2));
            mx1 = fmaxf(mx1, __shfl_xor_sync(0xffffffffu, mx1, 1));
            mx1 = fmaxf(mx1, __shfl_xor_sync(0xffffffffu, mx1, 2));
            float s0 = 0.f, s1 = 0.f;
#pragma unroll
            for (int nt = 0; nt < 8; nt++) {
                S[nt][0] = __expf(S[nt][0] - mx0); s0 += S[nt][0];
                S[nt][1] = __expf(S[nt][1] - mx0); s0 += S[nt][1];
                S[nt][2] = __expf(S[nt][2] - mx1); s1 += S[nt][2];
                S[nt][3] = __expf(S[nt][3] - mx1); s1 += S[nt][3];
            }
            // split UNNORMALIZED P; PV proceeds while the sum reduces
            uint32_t ph0[8], ph1[8], pl0[8], pl1[8];
#pragma unroll
            for (int nt = 0; nt < 8; nt++) {
                split2h(S[nt][0], S[nt][1], ph0[nt], pl0[nt]);
                split2h(S[nt][2], S[nt][3], ph1[nt], pl1[nt]);
            }
            float O[4][4];
#pragma unroll
            for (int dt = 0; dt < 4; dt++)
#pragma unroll
                for (int j = 0; j < 4; j++) O[dt][j] = 0.f;
#pragma unroll
            for (int kp = 0; kp < 4; kp++) {
                uint32_t ah0 = ph0[2*kp], ah1 = ph1[2*kp], ah2 = ph0[2*kp+1], ah3 = ph1[2*kp+1];
                uint32_t al0 = pl0[2*kp], al1 = pl1[2*kp], al2 = pl0[2*kp+1], al3 = pl1[2*kp+1];
                uint4 Bv[4];
#pragma unroll
                for (int dt = 0; dt < 4; dt++) {
                    int d = h * 32 + dt * 8 + gid;
                    Bv[dt] = *reinterpret_cast<const uint4*>(
                        VTS + d * VSTR + ((kp + d) & 3) * 16 + tg * 4);
                }
#pragma unroll
                for (int dt = 0; dt < 4; dt++)
                    MMAH(O[dt], ah0, ah1, ah2, ah3, Bv[dt].x, Bv[dt].y);
#pragma unroll
                for (int dt = 0; dt < 4; dt++)
                    MMAH(O[dt], al0, al1, al2, al3, Bv[dt].x, Bv[dt].y);
#pragma unroll
                for (int dt = 0; dt < 4; dt++)
                    MMAH(O[dt], ah0, ah1, ah2, ah3, Bv[dt].z, Bv[dt].w);
            }
            s0 += __shfl_xor_sync(0xffffffffu, s0, 1);
            s0 += __shfl_xor_sync(0xffffffffu, s0, 2);
            s1 += __shfl_xor_sync(0xffffffffu, s1, 1);
            s1 += __shfl_xor_sync(0xffffffffu, s1, 2);
            float inv0 = 1.f / s0, inv1 = 1.f / s1;
#pragma unroll
            for (int dt = 0; dt < 4; dt++) {
                O[dt][0] *= inv0; O[dt][1] *= inv0;
                O[dt][2] *= inv1; O[dt][3] *= inv1;
            }
            // store O (F4) into QS chunks 2h/2h+1 (head-private cols, rows r0/r1)
#pragma unroll
            for (int gg = 0; gg < 2; gg++) {
                uint32_t e0, f0, e1, f1;
                split2h(O[2*gg][0], O[2*gg][1], e0, f0);
                split2h(O[2*gg+1][0], O[2*gg+1][1], e1, f1);
                *reinterpret_cast<uint4*>(QS + r0 * XSTR + (2*h + gg) * 16 + tg * 4) =
                    make_uint4(e0, e1, f0, f1);
                split2h(O[2*gg][2], O[2*gg][3], e0, f0);
                split2h(O[2*gg+1][2], O[2*gg+1][3], e1, f1);
                *reinterpret_cast<uint4*>(QS + r1 * XSTR + (2*h + gg) * 16 + tg * 4) =
                    make_uint4(e0, e1, f0, f1);
            }
        }
    }
    __syncthreads();   // O (in QS) visible before Z gemm

    // ---- Z = O wo^T + bo -> global with inverse cyclic shift
    gemm_proj(QS, g_wh + 3 * 32768, acc, rbase, warpN, gid, tg);
    {
#pragma unroll
        for (int i = 0; i < 2; i++) {
            int r = rbase + i * 8 + gid;
            int rr = r >> 3, cc = r & 7;
            int oh = (wh * 8 + rr + 12) & 15, ow = (ww * 8 + cc + 12) & 15;
            float* d = out + ((size_t)(b * 16 + oh) * 16 + ow) * 256;
#pragma unroll
            for (int nf = 0; nf < 8; nf++) {
                int c = warpN * 64 + nf * 8 + 2 * tg;
                float2 bb = *reinterpret_cast<const float2*>(bo + c);
                float2 z = {acc[nf][i*2] + bb.x, acc[nf][i*2+1] + bb.y};
                *reinterpret_cast<float2*>(d + c) = z;
            }
        }
    }
}

// ---------------------------------------------------------------------------
extern "C" void kernel_launch(void* const* d_in, const int* in_sizes, int n_in,
                              void* d_out, int out_size)
{
    const float* img = (const float*)d_in[0];
    const float* wq  = (const float*)d_in[1];
    const float* bq  = (const float*)d_in[2];
    const float* wk  = (const float*)d_in[3];
    const float* bk  = (const float*)d_in[4];
    const float* wv  = (const float*)d_in[5];
    const float* bv  = (const float*)d_in[6];
    const float* wo  = (const float*)d_in[7];
    const float* bo  = (const float*)d_in[8];
    const float* ls  = (const float*)d_in[9];
    const float* cw1 = (const float*)d_in[10];
    const float* cb1 = (const float*)d_in[11];
    const float* cw2 = (const float*)d_in[12];
    (void)in_sizes; (void)n_in; (void)out_size;

    cudaFuncSetAttribute(swin_kernel,
                         cudaFuncAttributeMaxDynamicSharedMemorySize,
                         SMEM_U32 * 4);

    prep_kernel<<<289, 256>>>(cw1, cb1, cw2, wq, wk, wv, wo);
    swin_kernel<<<2048, 512, SMEM_U32 * 4>>>(img, bq, bk, bv, bo, ls,
                                             (float*)d_out);
}

// round 15
// speedup vs baseline: 1.0001x; 1.0001x over previous
#include <cuda_runtime.h>
#include <cuda_fp16.h>
#include <math.h>
#include <stdint.h>

// Swin-V2 shifted-window MHA: split-fp16 tensor-core (mma.m16n8k16.f16).
// One CTA (512 thr = 16 warps) per window; 2048 CTAs; 4 warps/SMSP.
// Projections: 2-term split (Ah*Bh + Al*Bh), W hi-only. Attention: 3-term,
// bias pre-loaded into the S accumulators (MMA C-op adds), P split inline
// per kp-group (minimal live registers; 512-thread RF cap is 128/thread).
// Weights read directly from global (L2-resident, fragment-ordered LDG.64,
// 1-chunk-ahead prefetch; cross-warp overlap hides the rest).
//
// "F4" layout (x, Q, K, O): u32 rows of XSTR; chunk g (16 values), group tg:
//   uint4 at row*XSTR + g*16 + tg*4 = {hi(pair g8+tg), hi(pair g8+tg+4), lo, lo}

#define XSTR 272
#define VSTR 64

#define OFF_X   0        // x F4 (17408); VT F4 (16384) overlays after V gemm
#define OFF_Q   17408    // Q F4 -> O F4
#define OFF_K   34816    // K F4
#define SMEM_U32 52224   // 208896 bytes

__device__ uint32_t g_wh[4 * 16 * 256 * 8];   // [w][kc][n][8] fp16-hi pairs
__device__ float    g_bias[4 * 8 * 64 * 64];  // [wtype][h][n][m], masked=-1e30

__device__ __forceinline__ uint32_t pack2h(float x, float y) {
    uint32_t r;
    asm("cvt.rn.f16x2.f32 %0, %1, %2;" : "=r"(r) : "f"(y), "f"(x));  // y->hi, x->lo
    return r;
}
__device__ __forceinline__ void split2h(float x, float y, uint32_t& h, uint32_t& l) {
    uint32_t hh;
    asm("cvt.rn.f16x2.f32 %0, %1, %2;" : "=r"(hh) : "f"(y), "f"(x));
    __half2 h2 = *reinterpret_cast<__half2*>(&hh);
    float rx = x - __half2float(__low2half(h2));
    float ry = y - __half2float(__high2half(h2));
    uint32_t ll;
    asm("cvt.rn.f16x2.f32 %0, %1, %2;" : "=r"(ll) : "f"(ry), "f"(rx));
    h = hh; l = ll;
}

#define MMAH(C, A0, A1, A2, A3, B0, B1)                                       \
    asm volatile("mma.sync.aligned.m16n8k16.row.col.f32.f16.f16.f32 "         \
                 "{%0,%1,%2,%3}, {%4,%5,%6,%7}, {%8,%9}, {%0,%1,%2,%3};"      \
                 : "+f"(C[0]), "+f"(C[1]), "+f"(C[2]), "+f"(C[3])             \
                 : "r"(A0), "r"(A1), "r"(A2), "r"(A3), "r"(B0), "r"(B1))

// ---------------------------------------------------------------------------
// Prep: blocks 0..63 = weight split; blocks 64..288 = masked bias table.
// ---------------------------------------------------------------------------
__global__ void prep_kernel(const float* __restrict__ w1,
                            const float* __restrict__ b1,
                            const float* __restrict__ w2,
                            const float* __restrict__ wq,
                            const float* __restrict__ wk,
                            const float* __restrict__ wv,
                            const float* __restrict__ wo)
{
    __shared__ float ws[8][8];
    __shared__ float bv[8];
    int t = threadIdx.x;

    if (blockIdx.x < 64) {
        const float* wsrc[4] = {wq, wk, wv, wo};
        int w = blockIdx.x >> 4, kc = blockIdx.x & 15;
        const float* src = wsrc[w] + t * 256 + kc * 16;
        float v[16];
#pragma unroll
        for (int i = 0; i < 4; i++) {
            float4 q = *reinterpret_cast<const float4*>(src + i * 4);
            v[4*i] = q.x; v[4*i+1] = q.y; v[4*i+2] = q.z; v[4*i+3] = q.w;
        }
        uint32_t u[8];
#pragma unroll
        for (int tg = 0; tg < 4; tg++) {
            u[tg*2]   = pack2h(v[2*tg],   v[2*tg+1]);
            u[tg*2+1] = pack2h(v[8+2*tg], v[9+2*tg]);
        }
        uint32_t* dst = g_wh + (blockIdx.x * 256 + t) * 8;
        *reinterpret_cast<uint4*>(dst)     = make_uint4(u[0], u[1], u[2], u[3]);
        *reinterpret_cast<uint4*>(dst + 4) = make_uint4(u[4], u[5], u[6], u[7]);
        return;
    }

    int cell = blockIdx.x - 64;           // 0..224
    int a = cell / 15, bcol = cell % 15;
    float ra = (a - 7) * (8.0f / 7.0f);
    float rb = (bcol - 7) * (8.0f / 7.0f);
    float va = (ra >= 0.f ? 1.f : -1.f) * log2f(fabsf(ra) + 1.f) * (1.f / 3.f);
    float vb = (rb >= 0.f ? 1.f : -1.f) * log2f(fabsf(rb) + 1.f) * (1.f / 3.f);

    int j1 = t, j2 = t + 256;
    float h1 = fmaxf(va * w1[j1 * 2] + vb * w1[j1 * 2 + 1] + b1[j1], 0.f);
    float h2 = fmaxf(va * w1[j2 * 2] + vb * w1[j2 * 2 + 1] + b1[j2], 0.f);

    float p[8];
#pragma unroll
    for (int h = 0; h < 8; h++)
        p[h] = h1 * w2[h * 512 + j1] + h2 * w2[h * 512 + j2];
#pragma unroll
    for (int h = 0; h < 8; h++)
#pragma unroll
        for (int off = 16; off; off >>= 1)
            p[h] += __shfl_xor_sync(0xffffffffu, p[h], off);

    int warp = t >> 5, lane = t & 31;
    if (lane == 0) {
#pragma unroll
        for (int h = 0; h < 8; h++) ws[warp][h] = p[h];
    }
    __syncthreads();
    if (t < 8) {
        float s = 0.f;
#pragma unroll
        for (int w = 0; w < 8; w++) s += ws[w][t];
        bv[t] = 16.f / (1.f + expf(-s));
    }
    __syncthreads();

    int da = a - 7, db = bcol - 7;
    int cntA = 8 - abs(da), cntB = 8 - abs(db);
    int rn0 = da > 0 ? da : 0, cn0 = db > 0 ? db : 0;
    int total = cntA * cntB * 32;
    for (int idx = t; idx < total; idx += 256) {
        int tmp = idx;
        int h = tmp & 7; tmp >>= 3;
        int wt_ = tmp & 3; tmp >>= 2;
        int pa = tmp / cntB, pb = tmp - pa * cntB;
        int rn = rn0 + pa, cn = cn0 + pb;
        int rm = rn - da, cm = cn - db;
        int wh = wt_ >> 1, ww = wt_ & 1;
        int ghn = wh * 8 + rn, gwn = ww * 8 + cn;
        int ghm = wh * 8 + rm, gwm = ww * 8 + cm;
        int gn = ((ghn < 8) ? 0 : (ghn < 12 ? 1 : 2)) * 3 + ((gwn < 8) ? 0 : (gwn < 12 ? 1 : 2));
        int gm = ((ghm < 8) ? 0 : (ghm < 12 ? 1 : 2)) * 3 + ((gwm < 8) ? 0 : (gwm < 12 ? 1 : 2));
        float val = (gn == gm) ? bv[h] : -1e30f;
        g_bias[((wt_ * 8 + h) * 64 + rn * 8 + cn) * 64 + rm * 8 + cm] = val;
    }
}

// ---- one 16-wide k-chunk, 16x64 warp tile (16 MMAs, hi then lo sweep) ----
#define PROJ_CHUNK(B, kc)                                                     \
    do {                                                                      \
        const uint32_t* a_ = ap + (kc) * 16;                                  \
        const uint4 A0 = *reinterpret_cast<const uint4*>(a_);                 \
        const uint4 A1 = *reinterpret_cast<const uint4*>(a_ + 8 * XSTR);      \
        _Pragma("unroll")                                                     \
        for (int nf = 0; nf < 8; nf++)                                        \
            MMAH(acc[nf], A0.x, A1.x, A0.y, A1.y, B[nf].x, B[nf].y);          \
        _Pragma("unroll")                                                     \
        for (int nf = 0; nf < 8; nf++)                                        \
            MMAH(acc[nf], A0.z, A1.z, A0.w, A1.w, B[nf].x, B[nf].y);          \
    } while (0)

#define PROJ_LD(B, c)                                                         \
    do {                                                                      \
        _Pragma("unroll")                                                     \
        for (int nf = 0; nf < 8; nf++) B[nf] = __ldg(gb + (c) * 1024 + nf * 32); \
    } while (0)

// ---------------------------------------------------------------------------
// Projection GEMM (2-term): out(64x256) = A(F4 smem) @ Whi^T. Warp 16x64.
// 1-chunk-ahead prefetch (2 buffers; minimal registers).
// ---------------------------------------------------------------------------
__device__ __forceinline__ void gemm_proj(
    const uint32_t* __restrict__ src, const uint32_t* __restrict__ gw,
    float acc[8][4], int rbase, int warpN, int gid, int tg)
{
#pragma unroll
    for (int nf = 0; nf < 8; nf++)
#pragma unroll
        for (int j = 0; j < 4; j++) acc[nf][j] = 0.f;

    const uint2* gb = reinterpret_cast<const uint2*>(gw) + (warpN * 64 + gid) * 4 + tg;
    const uint32_t* ap = src + (rbase + gid) * XSTR + tg * 4;

    uint2 Ba[8], Bb[8];
    PROJ_LD(Ba, 0);

#pragma unroll 1
    for (int it = 0; it < 8; it++) {
        PROJ_LD(Bb, 2 * it + 1);
        PROJ_CHUNK(Ba, 2 * it);
        if (it < 7) PROJ_LD(Ba, 2 * it + 2);
        PROJ_CHUNK(Bb, 2 * it + 1);
    }
}

// ---- VT chunk: 16 d-rows x 64 tokens, 16 MMAs (hi sweep then lo sweep) ----
#define VT_CHUNK(W, kc)                                                       \
    do {                                                                      \
        const uint32_t* xp = xp0 + (kc) * 16;                                 \
        uint4 Xv[8];                                                          \
        _Pragma("unroll")                                                     \
        for (int nf = 0; nf < 8; nf++)                                        \
            Xv[nf] = *reinterpret_cast<const uint4*>(xp + nf * 8 * XSTR);     \
        _Pragma("unroll")                                                     \
        for (int nf = 0; nf < 8; nf++)                                        \
            MMAH(av[nf], W[0].x, W[1].x, W[0].y, W[1].y, Xv[nf].x, Xv[nf].y); \
        _Pragma("unroll")                                                     \
        for (int nf = 0; nf < 8; nf++)                                        \
            MMAH(av[nf], W[0].x, W[1].x, W[0].y, W[1].y, Xv[nf].z, Xv[nf].w); \
    } while (0)

#define VT_LD(W, c)                                                           \
    do {                                                                      \
        W[0] = __ldg(ga + (c) * 1024);                                        \
        W[1] = __ldg(ga + (c) * 1024 + 32);                                   \
    } while (0)

// ---------------------------------------------------------------------------
// VT GEMM (2-term): VT(256x64) = Wv_hi @ x^T. Warp: 16 d-rows. Ends barrier.
// ---------------------------------------------------------------------------
__device__ __forceinline__ void gemm_vt(
    const uint32_t* __restrict__ x, const uint32_t* __restrict__ gw,
    float av[8][4], int warp, int gid, int tg)
{
#pragma unroll
    for (int nf = 0; nf < 8; nf++)
#pragma unroll
        for (int j = 0; j < 4; j++) av[nf][j] = 0.f;

    const uint2* ga = reinterpret_cast<const uint2*>(gw) + (warp * 16 + gid) * 4 + tg;
    const uint32_t* xp0 = x + gid * XSTR + tg * 4;

    uint2 Wa[2], Wb[2];
    VT_LD(Wa, 0);

#pragma unroll 1
    for (int it = 0; it < 8; it++) {
        VT_LD(Wb, 2 * it + 1);
        VT_CHUNK(Wa, 2 * it);
        if (it < 7) VT_LD(Wa, 2 * it + 2);
        VT_CHUNK(Wb, 2 * it + 1);
    }
    __syncthreads();   // all X reads complete before VTS overwrite
}

// ---------------------------------------------------------------------------
__global__ __launch_bounds__(512, 1)
void swin_kernel(const float* __restrict__ img,
                 const float* __restrict__ bq, const float* __restrict__ bk,
                 const float* __restrict__ bv, const float* __restrict__ bo,
                 const float* __restrict__ ls,
                 float* __restrict__ out)
{
    extern __shared__ uint32_t smu[];
    uint32_t* X   = smu + OFF_X;
    uint32_t* QS  = smu + OFF_Q;
    uint32_t* KS  = smu + OFF_K;
    uint32_t* VTS = smu + OFF_X;        // overlays X after V gemm

    const int t    = threadIdx.x;
    const int lane = t & 31;
    const int warp = t >> 5;            // 0..15
    const int warpM = warp & 3, warpN = warp >> 2;
    const int gid = lane >> 2, tg = lane & 3;
    const int blk = blockIdx.x;
    const int b   = blk >> 2;
    const int wh  = (blk >> 1) & 1, ww = blk & 1;
    const int wtype = blk & 3;

    // ---- load shifted window -> x F4 split (fp16 hi/lo)
    const float* imgb = img + (size_t)b * (16 * 16 * 256);
#pragma unroll
    for (int i = 0; i < 8; i++) {
        int f = i * 512 + t;            // float4 index
        int tok = f >> 6, c4 = f & 63;
        int r = tok >> 3, c = tok & 7;
        int ih = (wh * 8 + r + 12) & 15;
        int iw = (ww * 8 + c + 12) & 15;
        float4 v = *reinterpret_cast<const float4*>(&imgb[(ih * 16 + iw) * 256 + c4 * 4]);
        uint32_t h0, l0, h1, l1;
        split2h(v.x, v.y, h0, l0);
        split2h(v.z, v.w, h1, l1);
        int p0 = 2 * c4;
        int g = p0 >> 3, pos = p0 & 7;
        int tgs = pos & 3, slot = pos >> 2;
        uint32_t* base = X + tok * XSTR + g * 16 + slot;
        base[tgs * 4]           = h0;
        base[(tgs + 1) * 4]     = h1;
        base[tgs * 4 + 2]       = l0;
        base[(tgs + 1) * 4 + 2] = l1;
    }
    __syncthreads();   // X visible to all warps

    float acc[8][4];
    const int rbase = warpM * 16;
    const int r0w = rbase + gid, r1w = r0w + 8;

    // ---- Q = x wq^T + bq, cosine-normalize * scale, split -> QS
    gemm_proj(X, g_wh + 0 * 32768, acc, rbase, warpN, gid, tg);
    {
#pragma unroll
        for (int nf = 0; nf < 8; nf++) {
            float2 bb = *reinterpret_cast<const float2*>(bq + warpN * 64 + nf * 8 + 2 * tg);
            acc[nf][0] += bb.x; acc[nf][1] += bb.y;
            acc[nf][2] += bb.x; acc[nf][3] += bb.y;
        }
#pragma unroll
        for (int g = 0; g < 2; g++) {
            float ss0 = 0.f, ss1 = 0.f;
#pragma unroll
            for (int i = 0; i < 4; i++) {
                float* C = acc[4*g+i];
                ss0 += C[0]*C[0] + C[1]*C[1];
                ss1 += C[2]*C[2] + C[3]*C[3];
            }
            ss0 += __shfl_xor_sync(0xffffffffu, ss0, 1);
            ss0 += __shfl_xor_sync(0xffffffffu, ss0, 2);
            ss1 += __shfl_xor_sync(0xffffffffu, ss1, 1);
            ss1 += __shfl_xor_sync(0xffffffffu, ss1, 2);
            float sc = __expf(fminf(ls[warpN * 2 + g], 4.6051702f));
            float k0 = sc * rsqrtf(fmaxf(ss0, 1e-24f));
            float k1 = sc * rsqrtf(fmaxf(ss1, 1e-24f));
#pragma unroll
            for (int u = 0; u < 2; u++) {
                int ne = 4*g + 2*u, no = ne + 1;
                int ch = warpN * 4 + 2*g + u;
                uint32_t He, Le, Ho, Lo;
                split2h(acc[ne][0]*k0, acc[ne][1]*k0, He, Le);
                split2h(acc[no][0]*k0, acc[no][1]*k0, Ho, Lo);
                *reinterpret_cast<uint4*>(QS + r0w*XSTR + ch*16 + tg*4) = make_uint4(He, Ho, Le, Lo);
                split2h(acc[ne][2]*k1, acc[ne][3]*k1, He, Le);
                split2h(acc[no][2]*k1, acc[no][3]*k1, Ho, Lo);
                *reinterpret_cast<uint4*>(QS + r1w*XSTR + ch*16 + tg*4) = make_uint4(He, Ho, Le, Lo);
            }
        }
    }

    // ---- K = x wk^T + bk, normalize, split -> KS
    gemm_proj(X, g_wh + 1 * 32768, acc, rbase, warpN, gid, tg);
    {
#pragma unroll
        for (int nf = 0; nf < 8; nf++) {
            float2 bb = *reinterpret_cast<const float2*>(bk + warpN * 64 + nf * 8 + 2 * tg);
            acc[nf][0] += bb.x; acc[nf][1] += bb.y;
            acc[nf][2] += bb.x; acc[nf][3] += bb.y;
        }
#pragma unroll
        for (int g = 0; g < 2; g++) {
            float ss0 = 0.f, ss1 = 0.f;
#pragma unroll
            for (int i = 0; i < 4; i++) {
                float* C = acc[4*g+i];
                ss0 += C[0]*C[0] + C[1]*C[1];
                ss1 += C[2]*C[2] + C[3]*C[3];
            }
            ss0 += __shfl_xor_sync(0xffffffffu, ss0, 1);
            ss0 += __shfl_xor_sync(0xffffffffu, ss0, 2);
            ss1 += __shfl_xor_sync(0xffffffffu, ss1, 1);
            ss1 += __shfl_xor_sync(0xffffffffu, ss1, 2);
            float k0 = rsqrtf(fmaxf(ss0, 1e-24f));
            float k1 = rsqrtf(fmaxf(ss1, 1e-24f));
#pragma unroll
            for (int u = 0; u < 2; u++) {
                int ne = 4*g + 2*u, no = ne + 1;
                int ch = warpN * 4 + 2*g + u;
                uint32_t He, Le, Ho, Lo;
                split2h(acc[ne][0]*k0, acc[ne][1]*k0, He, Le);
                split2h(acc[no][0]*k0, acc[no][1]*k0, Ho, Lo);
                *reinterpret_cast<uint4*>(KS + r0w*XSTR + ch*16 + tg*4) = make_uint4(He, Ho, Le, Lo);
                split2h(acc[ne][2]*k1, acc[ne][3]*k1, He, Le);
                split2h(acc[no][2]*k1, acc[no][3]*k1, Ho, Lo);
                *reinterpret_cast<uint4*>(KS + r1w*XSTR + ch*16 + tg*4) = make_uint4(He, Ho, Le, Lo);
            }
        }
    }

    // ---- VT = wv x^T + bv (transposed V), F4 split -> VTS (overlays X)
    {
        float av[8][4];
        gemm_vt(X, g_wh + 2 * 32768, av, warp, gid, tg);
        int d0 = warp * 16 + gid, d1 = d0 + 8;
        float bv0 = bv[d0], bv1 = bv[d1];
#pragma unroll
        for (int kp = 0; kp < 4; kp++) {
            int ne = 2 * kp, no = ne + 1;
            uint32_t e0, f0, e1, f1;
            split2h(av[ne][0] + bv0, av[ne][1] + bv0, e0, f0);
            split2h(av[no][0] + bv0, av[no][1] + bv0, e1, f1);
            *reinterpret_cast<uint4*>(VTS + d0 * VSTR + ((kp + d0) & 3) * 16 + tg * 4) =
                make_uint4(e0, e1, f0, f1);
            split2h(av[ne][2] + bv1, av[ne][3] + bv1, e0, f0);
            split2h(av[no][2] + bv1, av[no][3] + bv1, e1, f1);
            *reinterpret_cast<uint4*>(VTS + d1 * VSTR + ((kp + d1) & 3) * 16 + tg * 4) =
                make_uint4(e0, e1, f0, f1);
        }
    }
    __syncthreads();   // QS/KS/VTS all visible before attention

    // ---- attention: warp = (half, head). Each warp: 2 mt tiles of 16 rows.
    //      Bias pre-loaded into S accumulators; P split inline per kp-group;
    //      softmax norm deferred past PV MMAs.
    {
        const int h = warp & 7;
        const int half = warp >> 3;
        const float NEG_INF = __int_as_float(0xff800000);
        const float* bias = g_bias + (wtype * 8 + h) * 4096;

#pragma unroll 1
        for (int i = 0; i < 2; i++) {
            const int mt = half * 2 + i;
            int r0 = mt * 16 + gid, r1 = r0 + 8;

            float S[8][4];
#pragma unroll
            for (int nt = 0; nt < 8; nt++) {
                float2 b0 = *reinterpret_cast<const float2*>(bias + r0 * 64 + nt * 8 + 2 * tg);
                float2 b1 = *reinterpret_cast<const float2*>(bias + r1 * 64 + nt * 8 + 2 * tg);
                S[nt][0] = b0.x; S[nt][1] = b0.y;
                S[nt][2] = b1.x; S[nt][3] = b1.y;
            }
#pragma unroll
            for (int kc = 0; kc < 2; kc++) {
                const uint4 A0 = *reinterpret_cast<const uint4*>(
                    QS + r0 * XSTR + (2 * h + kc) * 16 + tg * 4);
                const uint4 A1 = *reinterpret_cast<const uint4*>(
                    QS + r1 * XSTR + (2 * h + kc) * 16 + tg * 4);
#pragma unroll
                for (int gq = 0; gq < 2; gq++) {
                    uint4 Bv[4];
#pragma unroll
                    for (int j = 0; j < 4; j++)
                        Bv[j] = *reinterpret_cast<const uint4*>(
                            KS + ((gq * 4 + j) * 8 + gid) * XSTR + (2 * h + kc) * 16 + tg * 4);
#pragma unroll
                    for (int j = 0; j < 4; j++)
                        MMAH(S[gq*4+j], A0.x, A1.x, A0.y, A1.y, Bv[j].x, Bv[j].y);
#pragma unroll
                    for (int j = 0; j < 4; j++)
                        MMAH(S[gq*4+j], A0.z, A1.z, A0.w, A1.w, Bv[j].x, Bv[j].y);
#pragma unroll
                    for (int j = 0; j < 4; j++)
                        MMAH(S[gq*4+j], A0.x, A1.x, A0.y, A1.y, Bv[j].z, Bv[j].w);
                }
            }
            float mx0 = NEG_INF, mx1 = NEG_INF;
#pragma unroll
            for (int nt = 0; nt < 8; nt++) {
                mx0 = fmaxf(mx0, fmaxf(S[nt][0], S[nt][1]));
                mx1 = fmaxf(mx1, fmaxf(S[nt][2], S[nt][3]));
            }
            mx0 = fmaxf(mx0, __shfl_xor_sync(0xffffffffu, mx0, 1));
            mx0 = fmaxf(mx0, __shfl_xor_sync(0xffffffffu, mx0, 2));
            mx1 = fmaxf(mx1, __shfl_xor_sync(0xffffffffu, mx1, 1));
            mx1 = fmaxf(mx1, __shfl_xor_sync(0xffffffffu, mx1, 2));
            float s0 = 0.f, s1 = 0.f;
#pragma unroll
            for (int nt = 0; nt < 8; nt++) {
                S[nt][0] = __expf(S[nt][0] - mx0); s0 += S[nt][0];
                S[nt][1] = __expf(S[nt][1] - mx0); s0 += S[nt][1];
                S[nt][2] = __expf(S[nt][2] - mx1); s1 += S[nt][2];
                S[nt][3] = __expf(S[nt][3] - mx1); s1 += S[nt][3];
            }
            // PV with inline P-splitting (unnormalized); sum reduces below
            float O[4][4];
#pragma unroll
            for (int dt = 0; dt < 4; dt++)
#pragma unroll
                for (int j = 0; j < 4; j++) O[dt][j] = 0.f;
#pragma unroll
            for (int kp = 0; kp < 4; kp++) {
                uint32_t ah0, al0, ah1, al1, ah2, al2, ah3, al3;
                split2h(S[2*kp][0],   S[2*kp][1],   ah0, al0);
                split2h(S[2*kp][2],   S[2*kp][3],   ah1, al1);
                split2h(S[2*kp+1][0], S[2*kp+1][1], ah2, al2);
                split2h(S[2*kp+1][2], S[2*kp+1][3], ah3, al3);
                uint4 Bv[4];
#pragma unroll
                for (int dt = 0; dt < 4; dt++) {
                    int d = h * 32 + dt * 8 + gid;
                    Bv[dt] = *reinterpret_cast<const uint4*>(
                        VTS + d * VSTR + ((kp + d) & 3) * 16 + tg * 4);
                }
#pragma unroll
                for (int dt = 0; dt < 4; dt++)
                    MMAH(O[dt], ah0, ah1, ah2, ah3, Bv[dt].x, Bv[dt].y);
#pragma unroll
                for (int dt = 0; dt < 4; dt++)
                    MMAH(O[dt], al0, al1, al2, al3, Bv[dt].x, Bv[dt].y);
#pragma unroll
                for (int dt = 0; dt < 4; dt++)
                    MMAH(O[dt], ah0, ah1, ah2, ah3, Bv[dt].z, Bv[dt].w);
            }
            s0 += __shfl_xor_sync(0xffffffffu, s0, 1);
            s0 += __shfl_xor_sync(0xffffffffu, s0, 2);
            s1 += __shfl_xor_sync(0xffffffffu, s1, 1);
            s1 += __shfl_xor_sync(0xffffffffu, s1, 2);
            float inv0 = 1.f / s0, inv1 = 1.f / s1;
#pragma unroll
            for (int dt = 0; dt < 4; dt++) {
                O[dt][0] *= inv0; O[dt][1] *= inv0;
                O[dt][2] *= inv1; O[dt][3] *= inv1;
            }
            // store O (F4) into QS chunks 2h/2h+1 (head-private cols, rows r0/r1)
#pragma unroll
            for (int gg = 0; gg < 2; gg++) {
                uint32_t e0, f0, e1, f1;
                split2h(O[2*gg][0], O[2*gg][1], e0, f0);
                split2h(O[2*gg+1][0], O[2*gg+1][1], e1, f1);
                *reinterpret_cast<uint4*>(QS + r0 * XSTR + (2*h + gg) * 16 + tg * 4) =
                    make_uint4(e0, e1, f0, f1);
                split2h(O[2*gg][2], O[2*gg][3], e0, f0);
                split2h(O[2*gg+1][2], O[2*gg+1][3], e1, f1);
                *reinterpret_cast<uint4*>(QS + r1 * XSTR + (2*h + gg) * 16 + tg * 4) =
                    make_uint4(e0, e1, f0, f1);
            }
        }
    }
    __syncthreads();   // O (in QS) visible before Z gemm

    // ---- Z = O wo^T + bo -> global with inverse cyclic shift
    gemm_proj(QS, g_wh + 3 * 32768, acc, rbase, warpN, gid, tg);
    {
#pragma unroll
        for (int i = 0; i < 2; i++) {
            int r = rbase + i * 8 + gid;
            int rr = r >> 3, cc = r & 7;
            int oh = (wh * 8 + rr + 12) & 15, ow = (ww * 8 + cc + 12) & 15;
            float* d = out + ((size_t)(b * 16 + oh) * 16 + ow) * 256;
#pragma unroll
            for (int nf = 0; nf < 8; nf++) {
                int c = warpN * 64 + nf * 8 + 2 * tg;
                float2 bb = *reinterpret_cast<const float2*>(bo + c);
                float2 z = {acc[nf][i*2] + bb.x, acc[nf][i*2+1] + bb.y};
                *reinterpret_cast<float2*>(d + c) = z;
            }
        }
    }
}

// ---------------------------------------------------------------------------
extern "C" void kernel_launch(void* const* d_in, const int* in_sizes, int n_in,
                              void* d_out, int out_size)
{
    const float* img = (const float*)d_in[0];
    const float* wq  = (const float*)d_in[1];
    const float* bq  = (const float*)d_in[2];
    const float* wk  = (const float*)d_in[3];
    const float* bk  = (const float*)d_in[4];
    const float* wv  = (const float*)d_in[5];
    const float* bv  = (const float*)d_in[6];
    const float* wo  = (const float*)d_in[7];
    const float* bo  = (const float*)d_in[8];
    const float* ls  = (const float*)d_in[9];
    const float* cw1 = (const float*)d_in[10];
    const float* cb1 = (const float*)d_in[11];
    const float* cw2 = (const float*)d_in[12];
    (void)in_sizes; (void)n_in; (void)out_size;

    cudaFuncSetAttribute(swin_kernel,
                         cudaFuncAttributeMaxDynamicSharedMemorySize,
                         SMEM_U32 * 4);

    prep_kernel<<<289, 256>>>(cw1, cb1, cw2, wq, wk, wv, wo);
    swin_kernel<<<2048, 512, SMEM_U32 * 4>>>(img, bq, bk, bv, bo, ls,
                                             (float*)d_out);
}